// round 2
// baseline (speedup 1.0000x reference)
#include <cuda_runtime.h>
#include <cstdint>
#include <math.h>

#define B_ 16
#define L_ 2048
#define D_ 512
#define H_ 512

typedef unsigned long long ull;

// ---------------- static device scratch (no cudaMalloc allowed) -------------
__device__ float g_pre[(size_t)B_ * L_ * 1024];   // [b][t][fwd 0:512 | bwd 512:1024]
__device__ float g_hs [(size_t)B_ * L_ * 1024];   // same layout
__device__ float g_wxcat[512 * 1024];             // [k][n]  n<512: Wx_f, else Wx_b
__device__ float g_bcat[1024];
__device__ float g_wcomb[1024 * 512];             // rows 0:512 = Wo_f@Wd_top, 512:1024 = Wo_b@Wd_bot
__device__ float g_bias2[512];

// ---------------- f32x2 helpers ---------------------------------------------
__device__ __forceinline__ ull pk2(float x, float y) {
    ull r; asm("mov.b64 %0,{%1,%2};" : "=l"(r) : "f"(x), "f"(y)); return r;
}
__device__ __forceinline__ float2 up2(ull v) {
    float2 r; asm("mov.b64 {%0,%1},%2;" : "=f"(r.x), "=f"(r.y) : "l"(v)); return r;
}
__device__ __forceinline__ void fm2(ull& d, ull a, ull b) {
    asm("fma.rn.f32x2 %0,%1,%2,%0;" : "+l"(d) : "l"(a), "l"(b));
}

// ---------------- pack kernel: Wxcat / bcat ---------------------------------
__global__ void pack_kernel(const float* __restrict__ Wx_f, const float* __restrict__ Wx_b,
                            const float* __restrict__ b_f,  const float* __restrict__ b_b) {
    int idx = blockIdx.x * blockDim.x + threadIdx.x;   // 0 .. 524287
    int k = idx >> 10;
    int n = idx & 1023;
    g_wxcat[idx] = (n < 512) ? Wx_f[k * 512 + n] : Wx_b[k * 512 + (n - 512)];
    if (idx < 1024) g_bcat[idx] = (idx < 512) ? b_f[idx] : b_b[idx - 512];
}

// ---------------- bias2: fold bo_f, bo_b, bd through Wd ---------------------
__global__ void bias2_kernel(const float* __restrict__ Wd, const float* __restrict__ bd,
                             const float* __restrict__ bo_f, const float* __restrict__ bo_b) {
    int o = threadIdx.x;   // 512 threads
    float s = bd[o];
    for (int dd = 0; dd < 512; dd++) {
        s += bo_f[dd] * Wd[dd * 512 + o];
        s += bo_b[dd] * Wd[(512 + dd) * 512 + o];
    }
    g_bias2[o] = s;
}

// ---------------- generic SGEMM: C[m][n] = A[m][k]*B[k][n] + bias[n] --------
// lda == K, ldb == N, ldc == N. M,N multiples of 128; K multiple of 16.
#define TBM 128
#define TBN 128
#define TBK 16
__global__ void __launch_bounds__(256, 2)
sgemm(const float* __restrict__ A, const float* __restrict__ B,
      const float* __restrict__ bias, float* __restrict__ C,
      int M, int N, int K) {
    __shared__ float As[TBK][TBM + 4];
    __shared__ float Bs[TBK][TBN + 4];

    int tid = threadIdx.x;
    int bx = blockIdx.x, by = blockIdx.y;
    int tx = tid & 15, ty = tid >> 4;

    // load-role indices
    int mA  = tid >> 2;       // 0..63 (two rows: mA, mA+64)
    int kcA = tid & 3;        // float4 chunk along K
    int kbB = tid >> 5;       // 0..7 (two rows: kbB, kbB+8)
    int ncB = tid & 31;       // float4 chunk along N

    ull acc[8][4];
    #pragma unroll
    for (int i = 0; i < 8; i++)
        #pragma unroll
        for (int j = 0; j < 4; j++) acc[i][j] = 0ull;

    const float* Ag = A + (size_t)(by * TBM + mA) * K + kcA * 4;
    const float* Bg = B + (size_t)kbB * N + bx * TBN + ncB * 4;

    for (int k0 = 0; k0 < K; k0 += TBK) {
        float4 a0 = *(const float4*)(Ag + k0);
        float4 a1 = *(const float4*)(Ag + (size_t)64 * K + k0);
        float4 b0 = *(const float4*)(Bg + (size_t)k0 * N);
        float4 b1 = *(const float4*)(Bg + (size_t)(k0 + 8) * N);

        __syncthreads();   // previous compute done before overwriting tiles
        As[kcA * 4 + 0][mA] = a0.x;  As[kcA * 4 + 1][mA] = a0.y;
        As[kcA * 4 + 2][mA] = a0.z;  As[kcA * 4 + 3][mA] = a0.w;
        As[kcA * 4 + 0][mA + 64] = a1.x;  As[kcA * 4 + 1][mA + 64] = a1.y;
        As[kcA * 4 + 2][mA + 64] = a1.z;  As[kcA * 4 + 3][mA + 64] = a1.w;
        *(float4*)&Bs[kbB][ncB * 4]     = b0;
        *(float4*)&Bs[kbB + 8][ncB * 4] = b1;
        __syncthreads();

        #pragma unroll
        for (int kk = 0; kk < TBK; kk++) {
            float4 al = *(float4*)&As[kk][ty * 8];
            float4 ah = *(float4*)&As[kk][ty * 8 + 4];
            float4 bl = *(float4*)&Bs[kk][tx * 8];
            float4 bh = *(float4*)&Bs[kk][tx * 8 + 4];
            ull bb[4] = { pk2(bl.x, bl.y), pk2(bl.z, bl.w),
                          pk2(bh.x, bh.y), pk2(bh.z, bh.w) };
            float av[8] = { al.x, al.y, al.z, al.w, ah.x, ah.y, ah.z, ah.w };
            #pragma unroll
            for (int i = 0; i < 8; i++) {
                ull ad = pk2(av[i], av[i]);
                #pragma unroll
                for (int jn = 0; jn < 4; jn++) fm2(acc[i][jn], ad, bb[jn]);
            }
        }
    }

    int mBase = by * TBM + ty * 8;
    int nBase = bx * TBN + tx * 8;
    float4 bvl = make_float4(0.f, 0.f, 0.f, 0.f), bvh = bvl;
    if (bias) {
        bvl = *(const float4*)(bias + nBase);
        bvh = *(const float4*)(bias + nBase + 4);
    }
    #pragma unroll
    for (int i = 0; i < 8; i++) {
        float2 p0 = up2(acc[i][0]), p1 = up2(acc[i][1]);
        float2 p2 = up2(acc[i][2]), p3 = up2(acc[i][3]);
        float4 c0 = make_float4(p0.x + bvl.x, p0.y + bvl.y, p1.x + bvl.z, p1.y + bvl.w);
        float4 c1 = make_float4(p2.x + bvh.x, p2.y + bvh.y, p3.x + bvh.z, p3.y + bvh.w);
        float* cp = C + (size_t)(mBase + i) * N + nBase;
        *(float4*)cp = c0;
        *(float4*)(cp + 4) = c1;
    }
}

// ---------------- recurrence: 16 clusters x 8 CTAs --------------------------
// cluster cid: dir = cid>>3, batch pair = cid&7 -> batches 2p, 2p+1
// CTA rank r owns output columns [64r, 64r+64).
// SMEM: Wsh[64][512] (swizzled, [j][k]) | hbuf[2][2][512] | part[8][2][64]
#define RNN_SMEM_FLOATS (64 * 512 + 2 * 2 * 512 + 8 * 2 * 64)
#define RNN_SMEM_BYTES  (RNN_SMEM_FLOATS * 4)

__device__ __forceinline__ void st_cluster_f32(uint32_t saddr, uint32_t rank, float v) {
    uint32_t ra;
    asm volatile("mapa.shared::cluster.u32 %0, %1, %2;" : "=r"(ra) : "r"(saddr), "r"(rank));
    asm volatile("st.shared::cluster.f32 [%0], %1;" :: "r"(ra), "f"(v) : "memory");
}
__device__ __forceinline__ void cluster_sync_() {
    asm volatile("barrier.cluster.arrive.aligned;" ::: "memory");
    asm volatile("barrier.cluster.wait.aligned;" ::: "memory");
}

__global__ void __launch_bounds__(512, 1) __cluster_dims__(8, 1, 1)
rnn_scan(const float* __restrict__ Wh_f, const float* __restrict__ Wh_b) {
    extern __shared__ float smem[];
    float* Wsh  = smem;                    // 32768 floats
    float* hbuf = smem + 64 * 512;         // 2048 floats: [buf][b][512]
    float* part = hbuf + 2048;             // 1024 floats: [kq][b][64]

    int tid  = threadIdx.x;
    int bid  = blockIdx.x;
    int rank = bid & 7;
    int cid  = bid >> 3;
    int dir  = cid >> 3;                   // 0 fwd, 1 bwd
    int pair = cid & 7;
    int b0 = pair * 2;
    int jbase = rank * 64;
    const float* Wh = dir ? Wh_b : Wh_f;

    // ---- load + transpose + swizzle the Wh column slice: Wsh[j][k] ----
    {
        int k = tid;                  // 0..511
        int kc = k >> 2, kr = k & 3;
        #pragma unroll 4
        for (int c = 0; c < 16; c++) {
            float4 w = *(const float4*)(Wh + (size_t)k * H_ + jbase + 4 * c);
            float wv[4] = { w.x, w.y, w.z, w.w };
            #pragma unroll
            for (int i = 0; i < 4; i++) {
                int j = 4 * c + i;
                Wsh[j * 512 + ((kc ^ (j & 7)) << 2) + kr] = wv[i];
            }
        }
    }
    // zero both h buffers
    for (int i = tid; i < 2048; i += 512) hbuf[i] = 0.f;
    __syncthreads();
    cluster_sync_();   // everyone initialized before any peer pushes arrive

    int j  = tid & 63;
    int kq = tid >> 6;          // warp-uniform
    int kb = kq * 64;

    for (int s = 0; s < L_; s++) {
        int t   = dir ? (L_ - 1 - s) : s;
        int cur = s & 1;
        int nxt = cur ^ 1;

        // early prefetch of pre for the reduce threads (hidden under k-loop)
        float pv = 0.f;
        if (tid < 128) {
            int rj = tid & 63, rb = tid >> 6;
            int bg = b0 + rb;
            pv = __ldg(&g_pre[((size_t)bg * L_ + t) * 1024 + dir * 512 + jbase + rj]);
        }

        // ---- partial dot products over this thread's k range ----
        const float* hc = hbuf + cur * 1024;
        float acc0 = 0.f, acc1 = 0.f;
        #pragma unroll
        for (int c = 0; c < 16; c++) {
            int kk = kb + 4 * c;
            float4 w  = *(float4*)(Wsh + j * 512 + (((kk >> 2) ^ (j & 7)) << 2));
            float4 h0 = *(float4*)(hc + kk);
            float4 h1 = *(float4*)(hc + 512 + kk);
            acc0 = fmaf(w.x, h0.x, acc0); acc0 = fmaf(w.y, h0.y, acc0);
            acc0 = fmaf(w.z, h0.z, acc0); acc0 = fmaf(w.w, h0.w, acc0);
            acc1 = fmaf(w.x, h1.x, acc1); acc1 = fmaf(w.y, h1.y, acc1);
            acc1 = fmaf(w.z, h1.z, acc1); acc1 = fmaf(w.w, h1.w, acc1);
        }
        part[(kq * 2 + 0) * 64 + j] = acc0;
        part[(kq * 2 + 1) * 64 + j] = acc1;
        __syncthreads();

        // ---- reduce, tanh, publish ----
        if (tid < 128) {
            int rj = tid & 63, rb = tid >> 6;
            float sum = pv;
            #pragma unroll
            for (int q = 0; q < 8; q++) sum += part[(q * 2 + rb) * 64 + rj];
            float hn = tanhf(sum);

            int bg = b0 + rb;
            g_hs[((size_t)bg * L_ + t) * 1024 + dir * 512 + jbase + rj] = hn;

            int hidx = nxt * 1024 + rb * 512 + jbase + rj;
            hbuf[hidx] = hn;   // local copy
            uint32_t saddr = (uint32_t)__cvta_generic_to_shared(&hbuf[hidx]);
            #pragma unroll
            for (int p = 1; p < 8; p++)
                st_cluster_f32(saddr, (uint32_t)((rank + p) & 7), hn);
        }
        cluster_sync_();   // orders DSMEM pushes; also acts as CTA barrier
    }
}

// ---------------- host ------------------------------------------------------
extern "C" void kernel_launch(void* const* d_in, const int* in_sizes, int n_in,
                              void* d_out, int out_size) {
    const float* x    = (const float*)d_in[0];
    // d_in[1] = c (unused by reference)
    const float* Wx_f = (const float*)d_in[2];
    const float* Wh_f = (const float*)d_in[3];
    const float* b_f  = (const float*)d_in[4];
    const float* Wo_f = (const float*)d_in[5];
    const float* bo_f = (const float*)d_in[6];
    const float* Wx_b = (const float*)d_in[7];
    const float* Wh_b = (const float*)d_in[8];
    const float* b_b  = (const float*)d_in[9];
    const float* Wo_b = (const float*)d_in[10];
    const float* bo_b = (const float*)d_in[11];
    const float* Wd   = (const float*)d_in[12];
    const float* bd   = (const float*)d_in[13];
    float* out = (float*)d_out;

    void *p_pre, *p_hs, *p_wx, *p_bc, *p_wc, *p_b2;
    cudaGetSymbolAddress(&p_pre, g_pre);
    cudaGetSymbolAddress(&p_hs,  g_hs);
    cudaGetSymbolAddress(&p_wx,  g_wxcat);
    cudaGetSymbolAddress(&p_bc,  g_bcat);
    cudaGetSymbolAddress(&p_wc,  g_wcomb);
    cudaGetSymbolAddress(&p_b2,  g_bias2);

    // 1) pack Wx / biases
    pack_kernel<<<1024, 512>>>(Wx_f, Wx_b, b_f, b_b);

    // 2) pre = x @ Wxcat + bcat     [32768,512]@[512,1024]
    {
        dim3 g(1024 / TBN, (B_ * L_) / TBM);
        sgemm<<<g, 256>>>(x, (const float*)p_wx, (const float*)p_bc,
                          (float*)p_pre, B_ * L_, 1024, 512);
    }

    // 3) Wcomb = [Wo_f@Wd_top ; Wo_b@Wd_bot], bias2 (independent of scan)
    {
        dim3 g(512 / TBN, 512 / TBM);
        sgemm<<<g, 256>>>(Wo_f, Wd, nullptr, (float*)p_wc, 512, 512, 512);
        sgemm<<<g, 256>>>(Wo_b, Wd + 512 * 512, nullptr,
                          (float*)p_wc + 512 * 512, 512, 512, 512);
    }
    bias2_kernel<<<1, 512>>>(Wd, bd, bo_f, bo_b);

    // 4) bidirectional scan
    cudaFuncSetAttribute(rnn_scan, cudaFuncAttributeMaxDynamicSharedMemorySize,
                         RNN_SMEM_BYTES);
    {
        cudaLaunchConfig_t cfg = {};
        cfg.gridDim = dim3(128, 1, 1);
        cfg.blockDim = dim3(512, 1, 1);
        cfg.dynamicSmemBytes = RNN_SMEM_BYTES;
        cfg.stream = 0;
        cudaLaunchAttribute at[1];
        at[0].id = cudaLaunchAttributeClusterDimension;
        at[0].val.clusterDim.x = 8; at[0].val.clusterDim.y = 1; at[0].val.clusterDim.z = 1;
        cfg.attrs = at;
        cfg.numAttrs = 1;
        cudaLaunchKernelEx(&cfg, rnn_scan, Wh_f, Wh_b);
    }

    // 5) out = hs @ Wcomb + bias2   [32768,1024]@[1024,512]
    {
        dim3 g(512 / TBN, (B_ * L_) / TBM);
        sgemm<<<g, 256>>>((const float*)p_hs, (const float*)p_wc,
                          (const float*)p_b2, out, B_ * L_, 512, 1024);
    }
}

// round 3
// speedup vs baseline: 1.2817x; 1.2817x over previous
#include <cuda_runtime.h>
#include <cstdint>
#include <math.h>

#define B_ 16
#define L_ 2048
#define D_ 512
#define H_ 512

typedef unsigned long long ull;

// ---------------- static device scratch (no cudaMalloc allowed) -------------
__device__ float g_pre[(size_t)B_ * L_ * 1024];   // [b][t][fwd 0:512 | bwd 512:1024]
__device__ float g_hs [(size_t)B_ * L_ * 1024];   // same layout
__device__ float g_wxcat[512 * 1024];             // [k][n]  n<512: Wx_f, else Wx_b
__device__ float g_bcat[1024];
__device__ float g_wcomb[1024 * 512];             // rows 0:512 = Wo_f@Wd_top, 512:1024 = Wo_b@Wd_bot
__device__ float g_bias2[512];

// ---------------- f32x2 helpers ---------------------------------------------
__device__ __forceinline__ ull pk2(float x, float y) {
    ull r; asm("mov.b64 %0,{%1,%2};" : "=l"(r) : "f"(x), "f"(y)); return r;
}
__device__ __forceinline__ float2 up2(ull v) {
    float2 r; asm("mov.b64 {%0,%1},%2;" : "=f"(r.x), "=f"(r.y) : "l"(v)); return r;
}
__device__ __forceinline__ void fm2(ull& d, ull a, ull b) {
    asm("fma.rn.f32x2 %0,%1,%2,%0;" : "+l"(d) : "l"(a), "l"(b));
}

// ---------------- pack kernel: Wxcat / bcat ---------------------------------
__global__ void pack_kernel(const float* __restrict__ Wx_f, const float* __restrict__ Wx_b,
                            const float* __restrict__ b_f,  const float* __restrict__ b_b) {
    int idx = blockIdx.x * blockDim.x + threadIdx.x;   // 0 .. 524287
    int k = idx >> 10;
    int n = idx & 1023;
    g_wxcat[idx] = (n < 512) ? Wx_f[k * 512 + n] : Wx_b[k * 512 + (n - 512)];
    if (idx < 1024) g_bcat[idx] = (idx < 512) ? b_f[idx] : b_b[idx - 512];
}

// ---------------- bias2: fold bo_f, bo_b, bd through Wd ---------------------
__global__ void bias2_kernel(const float* __restrict__ Wd, const float* __restrict__ bd,
                             const float* __restrict__ bo_f, const float* __restrict__ bo_b) {
    int o = threadIdx.x;   // 512 threads
    float s = bd[o];
    for (int dd = 0; dd < 512; dd++) {
        s += bo_f[dd] * Wd[dd * 512 + o];
        s += bo_b[dd] * Wd[(512 + dd) * 512 + o];
    }
    g_bias2[o] = s;
}

// ---------------- generic SGEMM: C[m][n] = A[m][k]*B[k][n] + bias[n] --------
#define TBM 128
#define TBN 128
#define TBK 16
__global__ void __launch_bounds__(256, 2)
sgemm(const float* __restrict__ A, const float* __restrict__ B,
      const float* __restrict__ bias, float* __restrict__ C,
      int M, int N, int K) {
    __shared__ float As[TBK][TBM + 4];
    __shared__ float Bs[TBK][TBN + 4];

    int tid = threadIdx.x;
    int bx = blockIdx.x, by = blockIdx.y;
    int tx = tid & 15, ty = tid >> 4;

    int mA  = tid >> 2;       // 0..63 (two rows: mA, mA+64)
    int kcA = tid & 3;        // float4 chunk along K
    int kbB = tid >> 5;       // 0..7 (two rows: kbB, kbB+8)
    int ncB = tid & 31;       // float4 chunk along N

    ull acc[8][4];
    #pragma unroll
    for (int i = 0; i < 8; i++)
        #pragma unroll
        for (int j = 0; j < 4; j++) acc[i][j] = 0ull;

    const float* Ag = A + (size_t)(by * TBM + mA) * K + kcA * 4;
    const float* Bg = B + (size_t)kbB * N + bx * TBN + ncB * 4;

    for (int k0 = 0; k0 < K; k0 += TBK) {
        float4 a0 = *(const float4*)(Ag + k0);
        float4 a1 = *(const float4*)(Ag + (size_t)64 * K + k0);
        float4 b0 = *(const float4*)(Bg + (size_t)k0 * N);
        float4 b1 = *(const float4*)(Bg + (size_t)(k0 + 8) * N);

        __syncthreads();
        As[kcA * 4 + 0][mA] = a0.x;  As[kcA * 4 + 1][mA] = a0.y;
        As[kcA * 4 + 2][mA] = a0.z;  As[kcA * 4 + 3][mA] = a0.w;
        As[kcA * 4 + 0][mA + 64] = a1.x;  As[kcA * 4 + 1][mA + 64] = a1.y;
        As[kcA * 4 + 2][mA + 64] = a1.z;  As[kcA * 4 + 3][mA + 64] = a1.w;
        *(float4*)&Bs[kbB][ncB * 4]     = b0;
        *(float4*)&Bs[kbB + 8][ncB * 4] = b1;
        __syncthreads();

        #pragma unroll
        for (int kk = 0; kk < TBK; kk++) {
            float4 al = *(float4*)&As[kk][ty * 8];
            float4 ah = *(float4*)&As[kk][ty * 8 + 4];
            float4 bl = *(float4*)&Bs[kk][tx * 8];
            float4 bh = *(float4*)&Bs[kk][tx * 8 + 4];
            ull bb[4] = { pk2(bl.x, bl.y), pk2(bl.z, bl.w),
                          pk2(bh.x, bh.y), pk2(bh.z, bh.w) };
            float av[8] = { al.x, al.y, al.z, al.w, ah.x, ah.y, ah.z, ah.w };
            #pragma unroll
            for (int i = 0; i < 8; i++) {
                ull ad = pk2(av[i], av[i]);
                #pragma unroll
                for (int jn = 0; jn < 4; jn++) fm2(acc[i][jn], ad, bb[jn]);
            }
        }
    }

    int mBase = by * TBM + ty * 8;
    int nBase = bx * TBN + tx * 8;
    float4 bvl = make_float4(0.f, 0.f, 0.f, 0.f), bvh = bvl;
    if (bias) {
        bvl = *(const float4*)(bias + nBase);
        bvh = *(const float4*)(bias + nBase + 4);
    }
    #pragma unroll
    for (int i = 0; i < 8; i++) {
        float2 p0 = up2(acc[i][0]), p1 = up2(acc[i][1]);
        float2 p2 = up2(acc[i][2]), p3 = up2(acc[i][3]);
        float4 c0 = make_float4(p0.x + bvl.x, p0.y + bvl.y, p1.x + bvl.z, p1.y + bvl.w);
        float4 c1 = make_float4(p2.x + bvh.x, p2.y + bvh.y, p3.x + bvh.z, p3.y + bvh.w);
        float* cp = C + (size_t)(mBase + i) * N + nBase;
        *(float4*)cp = c0;
        *(float4*)(cp + 4) = c1;
    }
}

// ---------------- recurrence: 16 clusters x 8 CTAs --------------------------
// cluster cid: dir = cid>>3, batch pair = cid&7 -> batches 2p, 2p+1
// CTA rank r owns output columns [64r, 64r+64).
// Weights live ENTIRELY in registers: thread (j, kq) holds Wh[kb..kb+63][jbase+j]
// as 32 packed f32x2 k-pairs. SMEM only holds h (double-buffered) + partials.

__device__ __forceinline__ void st_cluster_f32(uint32_t saddr, uint32_t rank, float v) {
    uint32_t ra;
    asm volatile("mapa.shared::cluster.u32 %0, %1, %2;" : "=r"(ra) : "r"(saddr), "r"(rank));
    asm volatile("st.shared::cluster.f32 [%0], %1;" :: "r"(ra), "f"(v) : "memory");
}
__device__ __forceinline__ void cluster_sync_() {
    asm volatile("barrier.cluster.arrive.aligned;" ::: "memory");
    asm volatile("barrier.cluster.wait.aligned;" ::: "memory");
}

__global__ void __launch_bounds__(512, 1) __cluster_dims__(8, 1, 1)
rnn_scan(const float* __restrict__ Wh_f, const float* __restrict__ Wh_b) {
    __shared__ __align__(16) float hbuf[2 * 1024];   // [buf][b][512]
    __shared__ __align__(16) float part[1024];       // [kq*2+b][64]

    int tid  = threadIdx.x;
    int bid  = blockIdx.x;
    int rank = bid & 7;
    int cid  = bid >> 3;
    int dir  = cid >> 3;                   // 0 fwd, 1 bwd
    int pair = cid & 7;
    int b0 = pair * 2;
    int jbase = rank * 64;
    const float* __restrict__ Wh = dir ? Wh_b : Wh_f;

    int j  = tid & 63;
    int kq = tid >> 6;          // warp-uniform
    int kb = kq * 64;
    int jg = jbase + j;

    // ---- load this thread's weight column-slice into registers (k-pairs) ----
    ull w[32];
    #pragma unroll
    for (int c = 0; c < 32; c++) {
        float w0 = __ldg(&Wh[(size_t)(kb + 2 * c)     * H_ + jg]);
        float w1 = __ldg(&Wh[(size_t)(kb + 2 * c + 1) * H_ + jg]);
        w[c] = pk2(w0, w1);
    }

    for (int i = tid; i < 2048; i += 512) hbuf[i] = 0.f;
    __syncthreads();
    cluster_sync_();   // everyone initialized before any peer pushes arrive

    for (int s = 0; s < L_; s++) {
        int t   = dir ? (L_ - 1 - s) : s;
        int cur = s & 1;
        int nxt = cur ^ 1;

        // early prefetch of pre for the reduce threads (hidden under k-loop)
        float pv = 0.f;
        if (tid < 128) {
            int rj = tid & 63, rb = tid >> 6;
            int bg = b0 + rb;
            pv = __ldg(&g_pre[((size_t)bg * L_ + t) * 1024 + dir * 512 + jbase + rj]);
        }

        // ---- partial dot products over this thread's 64-wide k range --------
        const float* hc = hbuf + cur * 1024;
        ull a0x = 0ull, a0y = 0ull, a1x = 0ull, a1y = 0ull;
        #pragma unroll
        for (int c = 0; c < 16; c++) {
            ulonglong2 h0 = *(const ulonglong2*)(hc + kb + 4 * c);
            ulonglong2 h1 = *(const ulonglong2*)(hc + 512 + kb + 4 * c);
            fm2(a0x, w[2 * c],     h0.x);
            fm2(a0y, w[2 * c + 1], h0.y);
            fm2(a1x, w[2 * c],     h1.x);
            fm2(a1y, w[2 * c + 1], h1.y);
        }
        float2 p0x = up2(a0x), p0y = up2(a0y), p1x = up2(a1x), p1y = up2(a1y);
        part[(kq * 2 + 0) * 64 + j] = (p0x.x + p0x.y) + (p0y.x + p0y.y);
        part[(kq * 2 + 1) * 64 + j] = (p1x.x + p1x.y) + (p1y.x + p1y.y);
        __syncthreads();

        // ---- reduce, tanh, publish -----------------------------------------
        if (tid < 128) {
            int rj = tid & 63, rb = tid >> 6;
            float sum = pv;
            #pragma unroll
            for (int q = 0; q < 8; q++) sum += part[(q * 2 + rb) * 64 + rj];
            float hn = tanhf(sum);

            int bg = b0 + rb;
            g_hs[((size_t)bg * L_ + t) * 1024 + dir * 512 + jbase + rj] = hn;

            int hidx = nxt * 1024 + rb * 512 + jbase + rj;
            hbuf[hidx] = hn;   // local copy
            uint32_t saddr = (uint32_t)__cvta_generic_to_shared(&hbuf[hidx]);
            #pragma unroll
            for (int p = 1; p < 8; p++)
                st_cluster_f32(saddr, (uint32_t)((rank + p) & 7), hn);
        }
        cluster_sync_();   // orders DSMEM pushes; also separates part/hbuf phases
    }
}

// ---------------- host ------------------------------------------------------
extern "C" void kernel_launch(void* const* d_in, const int* in_sizes, int n_in,
                              void* d_out, int out_size) {
    const float* x    = (const float*)d_in[0];
    // d_in[1] = c (unused by reference)
    const float* Wx_f = (const float*)d_in[2];
    const float* Wh_f = (const float*)d_in[3];
    const float* b_f  = (const float*)d_in[4];
    const float* Wo_f = (const float*)d_in[5];
    const float* bo_f = (const float*)d_in[6];
    const float* Wx_b = (const float*)d_in[7];
    const float* Wh_b = (const float*)d_in[8];
    const float* b_b  = (const float*)d_in[9];
    const float* Wo_b = (const float*)d_in[10];
    const float* bo_b = (const float*)d_in[11];
    const float* Wd   = (const float*)d_in[12];
    const float* bd   = (const float*)d_in[13];
    float* out = (float*)d_out;

    void *p_pre, *p_hs, *p_wx, *p_bc, *p_wc, *p_b2;
    cudaGetSymbolAddress(&p_pre, g_pre);
    cudaGetSymbolAddress(&p_hs,  g_hs);
    cudaGetSymbolAddress(&p_wx,  g_wxcat);
    cudaGetSymbolAddress(&p_bc,  g_bcat);
    cudaGetSymbolAddress(&p_wc,  g_wcomb);
    cudaGetSymbolAddress(&p_b2,  g_bias2);

    // 1) pack Wx / biases
    pack_kernel<<<1024, 512>>>(Wx_f, Wx_b, b_f, b_b);

    // 2) pre = x @ Wxcat + bcat     [32768,512]@[512,1024]
    {
        dim3 g(1024 / TBN, (B_ * L_) / TBM);
        sgemm<<<g, 256>>>(x, (const float*)p_wx, (const float*)p_bc,
                          (float*)p_pre, B_ * L_, 1024, 512);
    }

    // 3) Wcomb = [Wo_f@Wd_top ; Wo_b@Wd_bot], bias2 (independent of scan)
    {
        dim3 g(512 / TBN, 512 / TBM);
        sgemm<<<g, 256>>>(Wo_f, Wd, nullptr, (float*)p_wc, 512, 512, 512);
        sgemm<<<g, 256>>>(Wo_b, Wd + 512 * 512, nullptr,
                          (float*)p_wc + 512 * 512, 512, 512, 512);
    }
    bias2_kernel<<<1, 512>>>(Wd, bd, bo_f, bo_b);

    // 4) bidirectional scan (weights in registers)
    {
        cudaLaunchConfig_t cfg = {};
        cfg.gridDim = dim3(128, 1, 1);
        cfg.blockDim = dim3(512, 1, 1);
        cfg.dynamicSmemBytes = 0;
        cfg.stream = 0;
        cudaLaunchAttribute at[1];
        at[0].id = cudaLaunchAttributeClusterDimension;
        at[0].val.clusterDim.x = 8; at[0].val.clusterDim.y = 1; at[0].val.clusterDim.z = 1;
        cfg.attrs = at;
        cfg.numAttrs = 1;
        cudaLaunchKernelEx(&cfg, rnn_scan, Wh_f, Wh_b);
    }

    // 5) out = hs @ Wcomb + bias2   [32768,1024]@[1024,512]
    {
        dim3 g(512 / TBN, (B_ * L_) / TBM);
        sgemm<<<g, 256>>>((const float*)p_hs, (const float*)p_wc,
                          (const float*)p_b2, out, B_ * L_, 512, 1024);
    }
}